// round 5
// baseline (speedup 1.0000x reference)
#include <cuda_runtime.h>
#include <cuda_bf16.h>
#include <cstdint>

// Problem constants
#define NROW 16384
#define DIMK 128

// log2(e) * 5  (exp(x/T) = 2^(x*5*log2e), T = 0.2)
#define K_EXP2 7.2134752044448170f

// GEMM tiling: CTA tile 256(M) x 128(N), warp tile 64x64, 8 warps (4m x 2n)
#define CTA_M 256
#define CTA_N 128
#define SMEM_BYTES (CTA_M * 256 + CTA_N * 256)   // 64KB A + 32KB B = 96KB

// Scratch (static device globals — no runtime allocation)
static __device__ __align__(16) __nv_bfloat16 g_v1[NROW * DIMK];
static __device__ __align__(16) __nv_bfloat16 g_v2[NROW * DIMK];
static __device__ float g_rowsum[NROW];
static __device__ float g_diag_part[NROW / 4];

__device__ __forceinline__ uint32_t smem_u32(const void* p) {
    uint32_t a;
    asm("{ .reg .u64 t; cvta.to.shared.u64 t, %1; cvt.u32.u64 %0, t; }"
        : "=r"(a) : "l"(p));
    return a;
}

__device__ __forceinline__ float ex2f(float x) {
    float r;
    asm("ex2.approx.f32 %0, %1;" : "=f"(r) : "f"(x));
    return r;
}

// ---------------------------------------------------------------------------
// Kernel 1: normalize rows (fp32), emit bf16 copies, per-block diag partials,
// and zero g_rowsum (each row written exactly once, before cl_gemm runs).
// One warp per row; 4 warps per block.
// ---------------------------------------------------------------------------
__global__ void __launch_bounds__(128) cl_prep(const float* __restrict__ emb) {
    __shared__ float sh_diag[4];
    int wid = threadIdx.x >> 5, lane = threadIdx.x & 31;
    int row = blockIdx.x * 4 + wid;

    const float4* r0 = (const float4*)(emb) + (size_t)row * (DIMK / 4) + lane;
    const float4* r1 = (const float4*)(emb + (size_t)NROW * DIMK) + (size_t)row * (DIMK / 4) + lane;
    float4 a = *r0;
    float4 b = *r1;

    float s00 = a.x * a.x + a.y * a.y + a.z * a.z + a.w * a.w;
    float s11 = b.x * b.x + b.y * b.y + b.z * b.z + b.w * b.w;
    float s01 = a.x * b.x + a.y * b.y + a.z * b.z + a.w * b.w;
#pragma unroll
    for (int m = 16; m; m >>= 1) {
        s00 += __shfl_xor_sync(0xffffffffu, s00, m);
        s11 += __shfl_xor_sync(0xffffffffu, s11, m);
        s01 += __shfl_xor_sync(0xffffffffu, s01, m);
    }
    // matches F.normalize: x / max(||x||, eps)
    float inv0 = 1.0f / fmaxf(sqrtf(s00), 1e-12f);
    float inv1 = 1.0f / fmaxf(sqrtf(s11), 1e-12f);

    __nv_bfloat162* o1 = (__nv_bfloat162*)g_v1 + (size_t)row * (DIMK / 2) + lane * 2;
    __nv_bfloat162* o2 = (__nv_bfloat162*)g_v2 + (size_t)row * (DIMK / 2) + lane * 2;
    o1[0] = __floats2bfloat162_rn(a.x * inv0, a.y * inv0);
    o1[1] = __floats2bfloat162_rn(a.z * inv0, a.w * inv0);
    o2[0] = __floats2bfloat162_rn(b.x * inv1, b.y * inv1);
    o2[1] = __floats2bfloat162_rn(b.z * inv1, b.w * inv1);

    if (lane == 0) {
        g_rowsum[row] = 0.0f;
        sh_diag[wid] = s01 * inv0 * inv1;
    }
    __syncthreads();
    if (threadIdx.x == 0)
        g_diag_part[blockIdx.x] = sh_diag[0] + sh_diag[1] + sh_diag[2] + sh_diag[3];
}

// ---------------------------------------------------------------------------
// Kernel 2: fused GEMM tile (mma.sync bf16 HMMA) + exp + per-row sums.
// CTA = 256x128 tile of sim = v1 @ v2^T, K=128 staged once in smem.
// 8 warps in 4(m) x 2(n) grid; warp tile 64x64 = 4x8 m16n8k16 tiles.
// SMEM: row-major [rows][128] bf16, 16B chunks XOR-swizzled: c' = c ^ (row&7)
// -> conflict-free ldmatrix and conflict-free stores.
// ---------------------------------------------------------------------------
__global__ void __launch_bounds__(256, 1) cl_gemm() {
    extern __shared__ __align__(1024) char smem[];
    char* As = smem;                      // 256 rows x 256B = 64KB
    char* Bs = smem + CTA_M * 256;        // 128 rows x 256B = 32KB

    int tid = threadIdx.x, wid = tid >> 5, lane = tid & 31;
    int tile_n = blockIdx.x, tile_m = blockIdx.y;

    // ---- global -> smem (swizzled) ----
    const uint4* asrc = (const uint4*)(g_v1 + (size_t)tile_m * CTA_M * DIMK);
    const uint4* bsrc = (const uint4*)(g_v2 + (size_t)tile_n * CTA_N * DIMK);
#pragma unroll
    for (int it = 0; it < 16; it++) {              // 4096 chunks of A
        int ci = tid + it * 256;
        int row = ci >> 4, c = ci & 15;
        uint32_t off = (uint32_t)row * 256u + (uint32_t)((c ^ (row & 7)) << 4);
        *(uint4*)(As + off) = asrc[ci];
    }
#pragma unroll
    for (int it = 0; it < 8; it++) {               // 2048 chunks of B
        int ci = tid + it * 256;
        int row = ci >> 4, c = ci & 15;
        uint32_t off = (uint32_t)row * 256u + (uint32_t)((c ^ (row & 7)) << 4);
        *(uint4*)(Bs + off) = bsrc[ci];
    }
    __syncthreads();

    const uint32_t sA = smem_u32(As);
    const uint32_t sB = smem_u32(Bs);

    int wm = wid & 3;        // warp row in 4x2 grid
    int wn = wid >> 2;       // warp col
    int row_base = wm * 64;  // warp's first tile row
    int col_base = wn * 64;  // warp's first tile col

    float acc[4][8][4];
#pragma unroll
    for (int mt = 0; mt < 4; mt++)
#pragma unroll
        for (int nt = 0; nt < 8; nt++)
#pragma unroll
            for (int k = 0; k < 4; k++) acc[mt][nt][k] = 0.0f;

    int lr = lane & 7;
    int q  = lane >> 3;      // 0..3 (ldmatrix matrix index group)

    // A fragment rows (per mt): lanes 0-7 rows 0-7, 8-15 rows 8-15 (k lo),
    // 16-23 rows 0-7, 24-31 rows 8-15 (k hi)
    int arow_r = row_base + (q & 1) * 8 + lr;        // relative m row (mt=0)
    int aqk    = q >> 1;                             // 0 = k lo chunk, 1 = k hi
    // B fragment rows (per nt2): lanes 0-15 n 0-7 (k lo/hi), 16-31 n 8-15
    int brow_r = col_base + (q >> 1) * 8 + lr;       // relative n row (nt2=0)
    int bqk    = q & 1;

#pragma unroll
    for (int s = 0; s < 8; s++) {
        // ---- A fragments (4 x ldmatrix.x4 -> 4 m-tiles of 16 rows) ----
        uint32_t a[4][4];
        {
            uint32_t kch = (uint32_t)(s * 2 + aqk);
#pragma unroll
            for (int mt = 0; mt < 4; mt++) {
                int ar = arow_r + mt * 16;
                uint32_t ad = sA + (uint32_t)ar * 256u + ((kch ^ (uint32_t)(ar & 7)) << 4);
                asm volatile("ldmatrix.sync.aligned.m8n8.x4.shared.b16 {%0,%1,%2,%3}, [%4];"
                             : "=r"(a[mt][0]), "=r"(a[mt][1]), "=r"(a[mt][2]), "=r"(a[mt][3])
                             : "r"(ad));
            }
        }
        // ---- B fragments (4 x ldmatrix.x4 -> 8 n-tiles) ----
        uint32_t b[4][4];
        {
            uint32_t kch = (uint32_t)(s * 2 + bqk);
#pragma unroll
            for (int nt2 = 0; nt2 < 4; nt2++) {
                int nr = brow_r + nt2 * 16;
                uint32_t bd = sB + (uint32_t)nr * 256u + ((kch ^ (uint32_t)(nr & 7)) << 4);
                asm volatile("ldmatrix.sync.aligned.m8n8.x4.shared.b16 {%0,%1,%2,%3}, [%4];"
                             : "=r"(b[nt2][0]), "=r"(b[nt2][1]), "=r"(b[nt2][2]), "=r"(b[nt2][3])
                             : "r"(bd));
            }
        }
        // ---- MMAs: 4 mt x 8 nt ----
#pragma unroll
        for (int nt2 = 0; nt2 < 4; nt2++) {
#pragma unroll
            for (int h = 0; h < 2; h++) {
                int nt = nt2 * 2 + h;
#pragma unroll
                for (int mt = 0; mt < 4; mt++) {
                    asm volatile(
                        "mma.sync.aligned.m16n8k16.row.col.f32.bf16.bf16.f32 "
                        "{%0,%1,%2,%3}, {%4,%5,%6,%7}, {%8,%9}, {%0,%1,%2,%3};"
                        : "+f"(acc[mt][nt][0]), "+f"(acc[mt][nt][1]),
                          "+f"(acc[mt][nt][2]), "+f"(acc[mt][nt][3])
                        : "r"(a[mt][0]), "r"(a[mt][1]), "r"(a[mt][2]), "r"(a[mt][3]),
                          "r"(b[nt2][h * 2]), "r"(b[nt2][h * 2 + 1]));
                }
            }
        }
    }

    // ---- epilogue: exp + row sums ----
    // m16n8 accum layout: d0,d1 -> row (lane>>2), d2,d3 -> row (lane>>2)+8
#pragma unroll
    for (int mt = 0; mt < 4; mt++) {
        float s0 = 0.0f, s1 = 0.0f;
#pragma unroll
        for (int nt = 0; nt < 8; nt++) {
            s0 += ex2f(acc[mt][nt][0] * K_EXP2) + ex2f(acc[mt][nt][1] * K_EXP2);
            s1 += ex2f(acc[mt][nt][2] * K_EXP2) + ex2f(acc[mt][nt][3] * K_EXP2);
        }
        // reduce across the 4 lanes of each accumulator quad (same row)
        s0 += __shfl_xor_sync(0xffffffffu, s0, 1);
        s0 += __shfl_xor_sync(0xffffffffu, s0, 2);
        s1 += __shfl_xor_sync(0xffffffffu, s1, 1);
        s1 += __shfl_xor_sync(0xffffffffu, s1, 2);
        if ((lane & 3) == 0) {
            int gr = tile_m * CTA_M + row_base + mt * 16 + (lane >> 2);
            atomicAdd(&g_rowsum[gr], s0);
            atomicAdd(&g_rowsum[gr + 8], s1);
        }
    }
}

// ---------------------------------------------------------------------------
// Kernel 3: loss = sum_i log(rowsum_i) - (sum diag partials)/T
// ---------------------------------------------------------------------------
__global__ void __launch_bounds__(1024) cl_finalize(float* __restrict__ out) {
    __shared__ float sh[1024];
    int tid = threadIdx.x;
    float s = 0.0f;
    for (int i = tid; i < NROW; i += 1024)
        s += __logf(g_rowsum[i]);
    for (int i = tid; i < NROW / 4; i += 1024)
        s -= 5.0f * g_diag_part[i];
    sh[tid] = s;
    __syncthreads();
    for (int d = 512; d > 0; d >>= 1) {
        if (tid < d) sh[tid] += sh[tid + d];
        __syncthreads();
    }
    if (tid == 0) out[0] = sh[0];
}

// ---------------------------------------------------------------------------
extern "C" void kernel_launch(void* const* d_in, const int* in_sizes, int n_in,
                              void* d_out, int out_size) {
    (void)in_sizes; (void)n_in; (void)out_size;
    const float* emb = (const float*)d_in[0];
    float* out = (float*)d_out;

    cudaFuncSetAttribute(cl_gemm, cudaFuncAttributeMaxDynamicSharedMemorySize,
                         SMEM_BYTES);

    cl_prep<<<NROW / 4, 128>>>(emb);
    cl_gemm<<<dim3(NROW / CTA_N, NROW / CTA_M), 256, SMEM_BYTES>>>();
    cl_finalize<<<1, 1024>>>(out);
}

// round 6
// speedup vs baseline: 1.4274x; 1.4274x over previous
#include <cuda_runtime.h>
#include <cuda_bf16.h>
#include <cstdint>

// Problem constants
#define NROW 16384
#define DIMK 128

// log2(e) * 5  (exp(x/T) = 2^(x*5*log2e), T = 0.2) — folded into v1 at prep.
#define K_EXP2 7.2134752044448170f

// Scratch (static device globals — no runtime allocation)
static __device__ __align__(16) __nv_bfloat16 g_v1[NROW * DIMK];  // pre-scaled by K_EXP2
static __device__ __align__(16) __nv_bfloat16 g_v2[NROW * DIMK];
static __device__ float g_rowsum[NROW];
static __device__ float g_diag_part[NROW / 4];

__device__ __forceinline__ uint32_t smem_u32(const void* p) {
    uint32_t a;
    asm("{ .reg .u64 t; cvta.to.shared.u64 t, %1; cvt.u32.u64 %0, t; }"
        : "=r"(a) : "l"(p));
    return a;
}

__device__ __forceinline__ float ex2f(float x) {
    float r;
    asm("ex2.approx.f32 %0, %1;" : "=f"(r) : "f"(x));
    return r;
}

__device__ __forceinline__ void cp_async16(uint32_t smem_dst, const void* gsrc) {
    asm volatile("cp.async.cg.shared.global [%0], [%1], 16;"
                 :: "r"(smem_dst), "l"(gsrc) : "memory");
}

// ---------------------------------------------------------------------------
// Kernel 1: normalize rows (fp32), emit bf16 copies (v1 pre-scaled by K_EXP2),
// per-block diag partials, and zero g_rowsum.
// One warp per row; 4 warps per block.
// ---------------------------------------------------------------------------
__global__ void __launch_bounds__(128) cl_prep(const float* __restrict__ emb) {
    __shared__ float sh_diag[4];
    int wid = threadIdx.x >> 5, lane = threadIdx.x & 31;
    int row = blockIdx.x * 4 + wid;

    const float4* r0 = (const float4*)(emb) + (size_t)row * (DIMK / 4) + lane;
    const float4* r1 = (const float4*)(emb + (size_t)NROW * DIMK) + (size_t)row * (DIMK / 4) + lane;
    float4 a = *r0;
    float4 b = *r1;

    float s00 = a.x * a.x + a.y * a.y + a.z * a.z + a.w * a.w;
    float s11 = b.x * b.x + b.y * b.y + b.z * b.z + b.w * b.w;
    float s01 = a.x * b.x + a.y * b.y + a.z * b.z + a.w * b.w;
#pragma unroll
    for (int m = 16; m; m >>= 1) {
        s00 += __shfl_xor_sync(0xffffffffu, s00, m);
        s11 += __shfl_xor_sync(0xffffffffu, s11, m);
        s01 += __shfl_xor_sync(0xffffffffu, s01, m);
    }
    // matches F.normalize: x / max(||x||, eps)
    float inv0 = 1.0f / fmaxf(sqrtf(s00), 1e-12f);
    float inv1 = 1.0f / fmaxf(sqrtf(s11), 1e-12f);
    float inv0s = inv0 * K_EXP2;   // fold exp scale into v1

    __nv_bfloat162* o1 = (__nv_bfloat162*)g_v1 + (size_t)row * (DIMK / 2) + lane * 2;
    __nv_bfloat162* o2 = (__nv_bfloat162*)g_v2 + (size_t)row * (DIMK / 2) + lane * 2;
    o1[0] = __floats2bfloat162_rn(a.x * inv0s, a.y * inv0s);
    o1[1] = __floats2bfloat162_rn(a.z * inv0s, a.w * inv0s);
    o2[0] = __floats2bfloat162_rn(b.x * inv1, b.y * inv1);
    o2[1] = __floats2bfloat162_rn(b.z * inv1, b.w * inv1);

    if (lane == 0) {
        g_rowsum[row] = 0.0f;
        sh_diag[wid] = s01 * inv0 * inv1;   // exact fp32 diagonal (unscaled)
    }
    __syncthreads();
    if (threadIdx.x == 0)
        g_diag_part[blockIdx.x] = sh_diag[0] + sh_diag[1] + sh_diag[2] + sh_diag[3];
}

// ---------------------------------------------------------------------------
// Kernel 2: fused GEMM tile (mma.sync bf16 HMMA) + exp + per-row sums.
// CTA = 128x128 tile of (K_EXP2 * sim) = (K_EXP2*v1) @ v2^T, K=128 in smem.
// 8 warps in 4(m) x 2(n) grid; warp tile 32x64 = 2x8 m16n8k16 tiles.
// SMEM: row-major [128][128] bf16, 16B chunks XOR-swizzled: c' = c ^ (row&7).
// 2 CTAs/SM (launch_bounds minblocks=2) so load phases overlap compute.
// ---------------------------------------------------------------------------
__global__ void __launch_bounds__(256, 2) cl_gemm() {
    extern __shared__ __align__(1024) char smem[];
    char* As = smem;
    char* Bs = smem + 32768;

    int tid = threadIdx.x, wid = tid >> 5, lane = tid & 31;
    int tile_n = blockIdx.x, tile_m = blockIdx.y;

    // ---- global -> smem via cp.async (swizzled), 8 x 16B per thread/tile ----
    const uint4* asrc = (const uint4*)(g_v1 + (size_t)tile_m * 128 * DIMK);
    const uint4* bsrc = (const uint4*)(g_v2 + (size_t)tile_n * 128 * DIMK);
    const uint32_t sA = smem_u32(As);
    const uint32_t sB = smem_u32(Bs);
#pragma unroll
    for (int it = 0; it < 8; it++) {
        int ci = tid + it * 256;
        int row = ci >> 4, c = ci & 15;
        uint32_t off = (uint32_t)row * 256u + (uint32_t)((c ^ (row & 7)) << 4);
        cp_async16(sA + off, asrc + ci);
        cp_async16(sB + off, bsrc + ci);
    }
    asm volatile("cp.async.commit_group;" ::: "memory");
    asm volatile("cp.async.wait_group 0;" ::: "memory");
    __syncthreads();

    int wm = wid & 3;        // warp row in 4x2 grid
    int wn = wid >> 2;       // warp col
    int row_base = wm * 32;  // warp's first tile row
    int col_base = wn * 64;  // warp's first tile col

    float acc[2][8][4];
#pragma unroll
    for (int mt = 0; mt < 2; mt++)
#pragma unroll
        for (int nt = 0; nt < 8; nt++)
#pragma unroll
            for (int k = 0; k < 4; k++) acc[mt][nt][k] = 0.0f;

    int lr = lane & 7;
    int q  = lane >> 5 ? 0 : (lane >> 3);   // 0..3
    q = lane >> 3;

    // A fragment rows: lanes 0-7 rows 0-7, 8-15 rows 8-15 (k lo),
    // 16-23 rows 0-7, 24-31 rows 8-15 (k hi)
    int arow0 = row_base + (q & 1) * 8 + lr;         // mt = 0
    int arow1 = arow0 + 16;                          // mt = 1
    int aqk   = q >> 1;
    // B fragment rows: lanes 0-15 n 0-7 (k lo/hi), 16-31 n 8-15
    int brow_r = col_base + (q >> 1) * 8 + lr;
    int bqk   = q & 1;

#pragma unroll
    for (int s = 0; s < 8; s++) {
        // ---- A fragments (2 x ldmatrix.x4) ----
        uint32_t a0[4], a1[4];
        {
            uint32_t kch = (uint32_t)(s * 2 + aqk);
            uint32_t ad0 = sA + (uint32_t)arow0 * 256u + ((kch ^ (uint32_t)(arow0 & 7)) << 4);
            uint32_t ad1 = sA + (uint32_t)arow1 * 256u + ((kch ^ (uint32_t)(arow1 & 7)) << 4);
            asm volatile("ldmatrix.sync.aligned.m8n8.x4.shared.b16 {%0,%1,%2,%3}, [%4];"
                         : "=r"(a0[0]), "=r"(a0[1]), "=r"(a0[2]), "=r"(a0[3]) : "r"(ad0));
            asm volatile("ldmatrix.sync.aligned.m8n8.x4.shared.b16 {%0,%1,%2,%3}, [%4];"
                         : "=r"(a1[0]), "=r"(a1[1]), "=r"(a1[2]), "=r"(a1[3]) : "r"(ad1));
        }
        // ---- B fragments (4 x ldmatrix.x4 -> 8 n-tiles) ----
        uint32_t b[4][4];
#pragma unroll
        for (int nt2 = 0; nt2 < 4; nt2++) {
            int nrow = brow_r + nt2 * 16;
            uint32_t kch = (uint32_t)(s * 2 + bqk);
            uint32_t bd = sB + (uint32_t)nrow * 256u + ((kch ^ (uint32_t)(nrow & 7)) << 4);
            asm volatile("ldmatrix.sync.aligned.m8n8.x4.shared.b16 {%0,%1,%2,%3}, [%4];"
                         : "=r"(b[nt2][0]), "=r"(b[nt2][1]), "=r"(b[nt2][2]), "=r"(b[nt2][3])
                         : "r"(bd));
        }
        // ---- MMAs ----
#pragma unroll
        for (int nt2 = 0; nt2 < 4; nt2++) {
#pragma unroll
            for (int h = 0; h < 2; h++) {
                int nt = nt2 * 2 + h;
                asm volatile(
                    "mma.sync.aligned.m16n8k16.row.col.f32.bf16.bf16.f32 "
                    "{%0,%1,%2,%3}, {%4,%5,%6,%7}, {%8,%9}, {%0,%1,%2,%3};"
                    : "+f"(acc[0][nt][0]), "+f"(acc[0][nt][1]),
                      "+f"(acc[0][nt][2]), "+f"(acc[0][nt][3])
                    : "r"(a0[0]), "r"(a0[1]), "r"(a0[2]), "r"(a0[3]),
                      "r"(b[nt2][h * 2]), "r"(b[nt2][h * 2 + 1]));
                asm volatile(
                    "mma.sync.aligned.m16n8k16.row.col.f32.bf16.bf16.f32 "
                    "{%0,%1,%2,%3}, {%4,%5,%6,%7}, {%8,%9}, {%0,%1,%2,%3};"
                    : "+f"(acc[1][nt][0]), "+f"(acc[1][nt][1]),
                      "+f"(acc[1][nt][2]), "+f"(acc[1][nt][3])
                    : "r"(a1[0]), "r"(a1[1]), "r"(a1[2]), "r"(a1[3]),
                      "r"(b[nt2][h * 2]), "r"(b[nt2][h * 2 + 1]));
            }
        }
    }

    // ---- epilogue: exp (scale pre-folded) + row sums ----
    // m16n8 accum layout: d0,d1 -> row (lane>>2), d2,d3 -> row (lane>>2)+8
#pragma unroll
    for (int mt = 0; mt < 2; mt++) {
        float s0 = 0.0f, s1 = 0.0f;
#pragma unroll
        for (int nt = 0; nt < 8; nt++) {
            s0 += ex2f(acc[mt][nt][0]) + ex2f(acc[mt][nt][1]);
            s1 += ex2f(acc[mt][nt][2]) + ex2f(acc[mt][nt][3]);
        }
        s0 += __shfl_xor_sync(0xffffffffu, s0, 1);
        s0 += __shfl_xor_sync(0xffffffffu, s0, 2);
        s1 += __shfl_xor_sync(0xffffffffu, s1, 1);
        s1 += __shfl_xor_sync(0xffffffffu, s1, 2);
        if ((lane & 3) == 0) {
            int gr = tile_m * 128 + row_base + mt * 16 + (lane >> 2);
            atomicAdd(&g_rowsum[gr], s0);
            atomicAdd(&g_rowsum[gr + 8], s1);
        }
    }
}

// ---------------------------------------------------------------------------
// Kernel 3: loss = sum_i log(rowsum_i) - (sum diag partials)/T
// ---------------------------------------------------------------------------
__global__ void __launch_bounds__(1024) cl_finalize(float* __restrict__ out) {
    __shared__ float sh[1024];
    int tid = threadIdx.x;
    float s = 0.0f;
    for (int i = tid; i < NROW; i += 1024)
        s += __logf(g_rowsum[i]);
    for (int i = tid; i < NROW / 4; i += 1024)
        s -= 5.0f * g_diag_part[i];
    sh[tid] = s;
    __syncthreads();
    for (int d = 512; d > 0; d >>= 1) {
        if (tid < d) sh[tid] += sh[tid + d];
        __syncthreads();
    }
    if (tid == 0) out[0] = sh[0];
}

// ---------------------------------------------------------------------------
extern "C" void kernel_launch(void* const* d_in, const int* in_sizes, int n_in,
                              void* d_out, int out_size) {
    (void)in_sizes; (void)n_in; (void)out_size;
    const float* emb = (const float*)d_in[0];
    float* out = (float*)d_out;

    cudaFuncSetAttribute(cl_gemm, cudaFuncAttributeMaxDynamicSharedMemorySize,
                         65536);

    cl_prep<<<NROW / 4, 128>>>(emb);
    cl_gemm<<<dim3(128, 128), 256, 65536>>>();
    cl_finalize<<<1, 1024>>>(out);
}